// round 1
// baseline (speedup 1.0000x reference)
#include <cuda_runtime.h>

// Problem constants (fixed by setup_inputs)
#define HH 256
#define WW 256
#define BB 4
#define C1 3
#define CC 64
#define KOFF 18          // 2*K*K
#define HWP (HH*WW)      // 65536

// Scratch (device-global; no allocation allowed)
__device__ float g_feat[BB*CC*HH*WW];     // 64 MiB
__device__ float g_off [BB*KOFF*HH*WW];   // 18 MiB

// ---------------------------------------------------------------------------
// Kernel 1: conv1  x[4,3,256,256] -> g_feat[4,64,256,256], 3x3 pad 1
// ---------------------------------------------------------------------------
__global__ __launch_bounds__(256) void conv1_kernel(
    const float* __restrict__ x, const float* __restrict__ w,
    const float* __restrict__ bias)
{
    __shared__ __align__(16) float w_sh[27][64];   // [c*9+kk][oc]
    __shared__ float b_sh[64];
    int tid = threadIdx.x;
    for (int idx = tid; idx < 64*27; idx += 256) {
        int oc = idx / 27, r = idx % 27;           // w: [oc][c][ky][kx]
        w_sh[r][oc] = w[idx];
    }
    if (tid < 64) b_sh[tid] = bias[tid];
    __syncthreads();

    int px  = blockIdx.x * 256 + tid;
    int b   = px >> 16;
    int rem = px & 0xFFFF;
    int oy  = rem >> 8, ox = rem & 255;

    float in[27];
    #pragma unroll
    for (int c = 0; c < 3; c++)
        #pragma unroll
        for (int ky = 0; ky < 3; ky++)
            #pragma unroll
            for (int kx = 0; kx < 3; kx++) {
                int iy = oy + ky - 1, ix = ox + kx - 1;
                bool ok = (iy >= 0 && iy < HH && ix >= 0 && ix < WW);
                in[c*9 + ky*3 + kx] = ok ? __ldg(&x[((b*3 + c)*HH + iy)*WW + ix]) : 0.f;
            }

    float acc[64];
    #pragma unroll
    for (int oc = 0; oc < 64; oc++) acc[oc] = b_sh[oc];

    #pragma unroll
    for (int r = 0; r < 27; r++) {
        float v = in[r];
        #pragma unroll
        for (int oc = 0; oc < 64; oc += 4) {
            float4 wv = *(const float4*)&w_sh[r][oc];
            acc[oc+0] += v * wv.x;  acc[oc+1] += v * wv.y;
            acc[oc+2] += v * wv.z;  acc[oc+3] += v * wv.w;
        }
    }
    int pix = oy*WW + ox;
    #pragma unroll
    for (int oc = 0; oc < 64; oc++)
        g_feat[(b*CC + oc)*HWP + pix] = acc[oc];
}

// ---------------------------------------------------------------------------
// Kernel 2: offset conv  g_feat -> g_off[4,18,256,256], 3x3 pad 1
// ---------------------------------------------------------------------------
__global__ __launch_bounds__(256) void offconv_kernel(
    const float* __restrict__ w, const float* __restrict__ bias)
{
    __shared__ __align__(16) float w_sh[576][20];  // [ic*9+kk][o], padded 18->20
    __shared__ float b_sh[18];
    int tid = threadIdx.x;
    for (int idx = tid; idx < 18*576; idx += 256) {
        int o = idx / 576, r = idx % 576;          // w: [o][ic][ky][kx]
        w_sh[r][o] = w[idx];
    }
    if (tid < 18) b_sh[tid] = bias[tid];
    __syncthreads();

    int px  = blockIdx.x * 256 + tid;
    int b   = px >> 16;
    int rem = px & 0xFFFF;
    int oy  = rem >> 8, ox = rem & 255;

    float acc[18];
    #pragma unroll
    for (int o = 0; o < 18; o++) acc[o] = b_sh[o];

    const float* fb = g_feat + b*CC*HWP;
    for (int ic = 0; ic < 64; ic++) {
        const float* p = fb + ic*HWP;
        float v[9];
        #pragma unroll
        for (int ky = 0; ky < 3; ky++)
            #pragma unroll
            for (int kx = 0; kx < 3; kx++) {
                int iy = oy + ky - 1, ix = ox + kx - 1;
                bool ok = (iy >= 0 && iy < HH && ix >= 0 && ix < WW);
                v[ky*3 + kx] = ok ? __ldg(&p[iy*WW + ix]) : 0.f;
            }
        #pragma unroll
        for (int kk = 0; kk < 9; kk++) {
            float s = v[kk];
            int r = ic*9 + kk;
            #pragma unroll
            for (int o = 0; o < 16; o += 4) {
                float4 wv = *(const float4*)&w_sh[r][o];
                acc[o+0] += s * wv.x;  acc[o+1] += s * wv.y;
                acc[o+2] += s * wv.z;  acc[o+3] += s * wv.w;
            }
            float2 wv2 = *(const float2*)&w_sh[r][16];
            acc[16] += s * wv2.x;  acc[17] += s * wv2.y;
        }
    }
    int pix = oy*WW + ox;
    #pragma unroll
    for (int o = 0; o < 18; o++)
        g_off[(b*KOFF + o)*HWP + pix] = acc[o];
}

// ---------------------------------------------------------------------------
// Kernel 3: deformable conv  (g_feat, g_off) -> out[4,64,256,256]
// weights staged in 147KB dynamic smem, [r=ic*9+k][oc]
// ---------------------------------------------------------------------------
extern __shared__ float smem3[];

__global__ __launch_bounds__(256, 1) void deform_kernel(
    const float* __restrict__ dw, const float* __restrict__ dbias,
    float* __restrict__ out)
{
    float* w_sh = smem3;              // 576*64 floats
    float* b_sh = smem3 + 576*64;     // 64 floats
    int tid = threadIdx.x;
    for (int idx = tid; idx < 64*576; idx += 256) {
        int oc = idx / 576, r = idx % 576;         // dw: [oc][ic][ky][kx]
        w_sh[r*64 + oc] = dw[idx];
    }
    if (tid < 64) b_sh[tid] = dbias[tid];
    __syncthreads();

    int px  = blockIdx.x * 256 + tid;
    int b   = px >> 16;
    int rem = px & 0xFFFF;
    int oy  = rem >> 8, ox = rem & 255;
    int pix = oy*WW + ox;

    float acc[64];
    #pragma unroll
    for (int oc = 0; oc < 64; oc++) acc[oc] = b_sh[oc];

    const float* fb = g_feat + b*CC*HWP;
    const float* ob = g_off  + b*KOFF*HWP;

    #pragma unroll 1
    for (int k = 0; k < 9; k++) {
        int i = k / 3, j = k % 3;
        float offy = __ldg(ob + (2*k    )*HWP + pix);
        float offx = __ldg(ob + (2*k + 1)*HWP + pix);
        float sy = (float)(oy - 1 + i) + offy;
        float sx = (float)(ox - 1 + j) + offx;

        float y0f = floorf(sy), x0f = floorf(sx);
        float dy = sy - y0f,    dx = sx - x0f;

        // per-corner validity on the UNCLIPPED float coordinate (ref semantics)
        bool vy0 = (y0f       >= 0.f) && (y0f       <= (float)(HH-1));
        bool vy1 = (y0f + 1.f >= 0.f) && (y0f + 1.f <= (float)(HH-1));
        bool vx0 = (x0f       >= 0.f) && (x0f       <= (float)(WW-1));
        bool vx1 = (x0f + 1.f >= 0.f) && (x0f + 1.f <= (float)(WW-1));

        int y0 = (int)fminf(fmaxf(y0f,       0.f), (float)(HH-1));
        int y1 = (int)fminf(fmaxf(y0f + 1.f, 0.f), (float)(HH-1));
        int x0 = (int)fminf(fmaxf(x0f,       0.f), (float)(WW-1));
        int x1 = (int)fminf(fmaxf(x0f + 1.f, 0.f), (float)(WW-1));

        float w00 = (1.f-dy)*(1.f-dx) * ((vy0 && vx0) ? 1.f : 0.f);
        float w01 = (1.f-dy)*dx       * ((vy0 && vx1) ? 1.f : 0.f);
        float w10 = dy*(1.f-dx)       * ((vy1 && vx0) ? 1.f : 0.f);
        float w11 = dy*dx             * ((vy1 && vx1) ? 1.f : 0.f);

        int i00 = y0*WW + x0, i01 = y0*WW + x1;
        int i10 = y1*WW + x0, i11 = y1*WW + x1;

        #pragma unroll 4
        for (int ic = 0; ic < 64; ic++) {
            const float* p = fb + ic*HWP;
            float s = w00*__ldg(p + i00) + w01*__ldg(p + i01)
                    + w10*__ldg(p + i10) + w11*__ldg(p + i11);
            const float* wr = w_sh + (ic*9 + k)*64;
            #pragma unroll
            for (int oc = 0; oc < 64; oc += 4) {
                float4 wv = *(const float4*)&wr[oc];
                acc[oc+0] += s * wv.x;  acc[oc+1] += s * wv.y;
                acc[oc+2] += s * wv.z;  acc[oc+3] += s * wv.w;
            }
        }
    }

    #pragma unroll
    for (int oc = 0; oc < 64; oc++)
        out[(b*CC + oc)*HWP + pix] = acc[oc];
}

// ---------------------------------------------------------------------------
extern "C" void kernel_launch(void* const* d_in, const int* in_sizes, int n_in,
                              void* d_out, int out_size)
{
    const float* x      = (const float*)d_in[0];
    const float* conv_w = (const float*)d_in[1];
    const float* conv_b = (const float*)d_in[2];
    const float* off_w  = (const float*)d_in[3];
    const float* off_b  = (const float*)d_in[4];
    const float* dw     = (const float*)d_in[5];
    const float* db     = (const float*)d_in[6];
    float* out = (float*)d_out;

    const int blocks = BB*HH*WW / 256;   // 1024

    conv1_kernel  <<<blocks, 256>>>(x, conv_w, conv_b);
    offconv_kernel<<<blocks, 256>>>(off_w, off_b);

    const int smem3_bytes = (576*64 + 64) * sizeof(float);   // 147712
    cudaFuncSetAttribute(deform_kernel,
                         cudaFuncAttributeMaxDynamicSharedMemorySize, smem3_bytes);
    deform_kernel <<<blocks, 256, smem3_bytes>>>(dw, db, out);
}

// round 2
// speedup vs baseline: 1.0669x; 1.0669x over previous
#include <cuda_runtime.h>

// Problem constants (fixed by setup_inputs)
#define HH 256
#define WW 256
#define BB 4
#define CC 64
#define KOFF 18          // 2*K*K
#define HWP (HH*WW)      // 65536

// Scratch (device-global; no allocation allowed)
__device__ float g_feat[BB*CC*HH*WW];     // 64 MiB
__device__ float g_off [BB*KOFF*HH*WW];   // 18 MiB

// ---------------------------------------------------------------------------
// Packed f32x2 helpers (FFMA2 — only reachable via PTX fma.rn.f32x2)
// ---------------------------------------------------------------------------
typedef unsigned long long u64;

__device__ __forceinline__ void fma2(u64 &d, u64 a, u64 b) {
    asm("fma.rn.f32x2 %0, %1, %2, %0;" : "+l"(d) : "l"(a), "l"(b));
}
__device__ __forceinline__ u64 pack2(float lo, float hi) {
    u64 r; asm("mov.b64 %0, {%1, %2};" : "=l"(r) : "f"(lo), "f"(hi)); return r;
}
__device__ __forceinline__ void unpack2(u64 v, float &lo, float &hi) {
    asm("mov.b64 {%0, %1}, %2;" : "=f"(lo), "=f"(hi) : "l"(v));
}

// ---------------------------------------------------------------------------
// Kernel 1: conv1  x[4,3,256,256] -> g_feat[4,64,256,256], 3x3 pad 1
// ---------------------------------------------------------------------------
__global__ __launch_bounds__(256) void conv1_kernel(
    const float* __restrict__ x, const float* __restrict__ w,
    const float* __restrict__ bias)
{
    __shared__ __align__(16) float w_sh[27][64];   // [c*9+kk][oc]
    __shared__ float b_sh[64];
    int tid = threadIdx.x;
    for (int idx = tid; idx < 64*27; idx += 256) {
        int oc = idx / 27, r = idx % 27;           // w: [oc][c][ky][kx]
        w_sh[r][oc] = w[idx];
    }
    if (tid < 64) b_sh[tid] = bias[tid];
    __syncthreads();

    int px  = blockIdx.x * 256 + tid;
    int b   = px >> 16;
    int rem = px & 0xFFFF;
    int oy  = rem >> 8, ox = rem & 255;

    float in[27];
    #pragma unroll
    for (int c = 0; c < 3; c++)
        #pragma unroll
        for (int ky = 0; ky < 3; ky++)
            #pragma unroll
            for (int kx = 0; kx < 3; kx++) {
                int iy = oy + ky - 1, ix = ox + kx - 1;
                bool ok = (iy >= 0 && iy < HH && ix >= 0 && ix < WW);
                in[c*9 + ky*3 + kx] = ok ? __ldg(&x[((b*3 + c)*HH + iy)*WW + ix]) : 0.f;
            }

    u64 acc[32];
    #pragma unroll
    for (int j = 0; j < 32; j++) acc[j] = pack2(b_sh[2*j], b_sh[2*j+1]);

    #pragma unroll
    for (int r = 0; r < 27; r++) {
        u64 v2 = pack2(in[r], in[r]);
        #pragma unroll
        for (int m = 0; m < 16; m++) {
            ulonglong2 wv = *(const ulonglong2*)&w_sh[r][4*m];
            fma2(acc[2*m],   wv.x, v2);
            fma2(acc[2*m+1], wv.y, v2);
        }
    }
    int pix = oy*WW + ox;
    #pragma unroll
    for (int j = 0; j < 32; j++) {
        float lo, hi; unpack2(acc[j], lo, hi);
        g_feat[(b*CC + 2*j  )*HWP + pix] = lo;
        g_feat[(b*CC + 2*j+1)*HWP + pix] = hi;
    }
}

// ---------------------------------------------------------------------------
// Kernel 2: offset conv  g_feat -> g_off[4,18,256,256], 3x3 pad 1
// ---------------------------------------------------------------------------
__global__ __launch_bounds__(256) void offconv_kernel(
    const float* __restrict__ w, const float* __restrict__ bias)
{
    __shared__ __align__(16) float w_sh[576][20];  // [ic*9+kk][o], padded 18->20
    __shared__ float b_sh[18];
    int tid = threadIdx.x;
    for (int idx = tid; idx < 18*576; idx += 256) {
        int o = idx / 576, r = idx % 576;          // w: [o][ic][ky][kx]
        w_sh[r][o] = w[idx];
    }
    if (tid < 18) b_sh[tid] = bias[tid];
    __syncthreads();

    int px  = blockIdx.x * 256 + tid;
    int b   = px >> 16;
    int rem = px & 0xFFFF;
    int oy  = rem >> 8, ox = rem & 255;

    u64 acc[9];
    #pragma unroll
    for (int j = 0; j < 9; j++) acc[j] = pack2(b_sh[2*j], b_sh[2*j+1]);

    const float* fb = g_feat + b*CC*HWP;
    for (int ic = 0; ic < 64; ic++) {
        const float* p = fb + ic*HWP;
        float v[9];
        #pragma unroll
        for (int ky = 0; ky < 3; ky++)
            #pragma unroll
            for (int kx = 0; kx < 3; kx++) {
                int iy = oy + ky - 1, ix = ox + kx - 1;
                bool ok = (iy >= 0 && iy < HH && ix >= 0 && ix < WW);
                v[ky*3 + kx] = ok ? __ldg(&p[iy*WW + ix]) : 0.f;
            }
        #pragma unroll
        for (int kk = 0; kk < 9; kk++) {
            u64 s2 = pack2(v[kk], v[kk]);
            int r = ic*9 + kk;
            #pragma unroll
            for (int m = 0; m < 4; m++) {
                ulonglong2 wv = *(const ulonglong2*)&w_sh[r][4*m];
                fma2(acc[2*m],   wv.x, s2);
                fma2(acc[2*m+1], wv.y, s2);
            }
            u64 wt = *(const u64*)&w_sh[r][16];
            fma2(acc[8], wt, s2);
        }
    }
    int pix = oy*WW + ox;
    #pragma unroll
    for (int j = 0; j < 9; j++) {
        float lo, hi; unpack2(acc[j], lo, hi);
        g_off[(b*KOFF + 2*j  )*HWP + pix] = lo;
        g_off[(b*KOFF + 2*j+1)*HWP + pix] = hi;
    }
}

// ---------------------------------------------------------------------------
// Kernel 3: deformable conv  (g_feat, g_off) -> out[4,64,256,256]
// 2 adjacent pixels / thread, FFMA2 accumulators, weights in 147KB dyn smem
// ---------------------------------------------------------------------------
struct Samp { float w00, w01, w10, w11; int i00, i01, i10, i11; };

__device__ __forceinline__ Samp make_samp(float sy, float sx)
{
    float y0f = floorf(sy), x0f = floorf(sx);
    float dy = sy - y0f,    dx = sx - x0f;

    // per-corner validity on the UNCLIPPED float coordinate (ref semantics)
    bool vy0 = (y0f       >= 0.f) && (y0f       <= (float)(HH-1));
    bool vy1 = (y0f + 1.f >= 0.f) && (y0f + 1.f <= (float)(HH-1));
    bool vx0 = (x0f       >= 0.f) && (x0f       <= (float)(WW-1));
    bool vx1 = (x0f + 1.f >= 0.f) && (x0f + 1.f <= (float)(WW-1));

    int y0 = (int)fminf(fmaxf(y0f,       0.f), (float)(HH-1));
    int y1 = (int)fminf(fmaxf(y0f + 1.f, 0.f), (float)(HH-1));
    int x0 = (int)fminf(fmaxf(x0f,       0.f), (float)(WW-1));
    int x1 = (int)fminf(fmaxf(x0f + 1.f, 0.f), (float)(WW-1));

    Samp s;
    s.w00 = (1.f-dy)*(1.f-dx) * ((vy0 && vx0) ? 1.f : 0.f);
    s.w01 = (1.f-dy)*dx       * ((vy0 && vx1) ? 1.f : 0.f);
    s.w10 = dy*(1.f-dx)       * ((vy1 && vx0) ? 1.f : 0.f);
    s.w11 = dy*dx             * ((vy1 && vx1) ? 1.f : 0.f);
    s.i00 = y0*WW + x0;  s.i01 = y0*WW + x1;
    s.i10 = y1*WW + x0;  s.i11 = y1*WW + x1;
    return s;
}

extern __shared__ float smem3[];

__global__ __launch_bounds__(256, 1) void deform_kernel(
    const float* __restrict__ dw, const float* __restrict__ dbias,
    float* __restrict__ out)
{
    float* w_sh = smem3;              // 576*64 floats, [r=ic*9+k][oc]
    float* b_sh = smem3 + 576*64;     // 64 floats
    int tid = threadIdx.x;
    for (int idx = tid; idx < 64*576; idx += 256) {
        int oc = idx / 576, r = idx % 576;         // dw: [oc][ic][ky][kx]
        w_sh[r*64 + oc] = dw[idx];
    }
    if (tid < 64) b_sh[tid] = dbias[tid];
    __syncthreads();

    int t    = blockIdx.x * 256 + tid;   // 131072 threads total
    int px0  = t * 2;                    // even pixel; px1 = px0+1 same row
    int b    = px0 >> 16;
    int rem  = px0 & 0xFFFF;
    int oy   = rem >> 8, ox0 = rem & 255;
    int pix0 = oy*WW + ox0;

    u64 accA[32], accB[32];
    #pragma unroll
    for (int j = 0; j < 32; j++) {
        u64 bi = pack2(b_sh[2*j], b_sh[2*j+1]);
        accA[j] = bi; accB[j] = bi;
    }

    const float* fb = g_feat + b*CC*HWP;
    const float* ob = g_off  + b*KOFF*HWP;

    #pragma unroll 1
    for (int k = 0; k < 9; k++) {
        int i = k / 3, j = k % 3;
        float2 ofy = __ldg((const float2*)(ob + (2*k    )*HWP + pix0));
        float2 ofx = __ldg((const float2*)(ob + (2*k + 1)*HWP + pix0));

        Samp A = make_samp((float)(oy - 1 + i) + ofy.x,
                           (float)(ox0 - 1 + j) + ofx.x);
        Samp B = make_samp((float)(oy - 1 + i) + ofy.y,
                           (float)(ox0 + j) + ofx.y);   // ox1-1+j = ox0+j

        #pragma unroll 2
        for (int ic = 0; ic < 64; ic++) {
            const float* p = fb + ic*HWP;
            float sA = A.w00*__ldg(p + A.i00) + A.w01*__ldg(p + A.i01)
                     + A.w10*__ldg(p + A.i10) + A.w11*__ldg(p + A.i11);
            float sB = B.w00*__ldg(p + B.i00) + B.w01*__ldg(p + B.i01)
                     + B.w10*__ldg(p + B.i10) + B.w11*__ldg(p + B.i11);
            u64 sA2 = pack2(sA, sA);
            u64 sB2 = pack2(sB, sB);
            const float* wr = w_sh + (ic*9 + k)*64;
            #pragma unroll
            for (int m = 0; m < 16; m++) {
                ulonglong2 wv = *(const ulonglong2*)(wr + 4*m);
                fma2(accA[2*m],   wv.x, sA2);
                fma2(accA[2*m+1], wv.y, sA2);
                fma2(accB[2*m],   wv.x, sB2);
                fma2(accB[2*m+1], wv.y, sB2);
            }
        }
    }

    #pragma unroll
    for (int j = 0; j < 32; j++) {
        float a0, a1, b0, b1;
        unpack2(accA[j], a0, a1);
        unpack2(accB[j], b0, b1);
        float2 v0 = make_float2(a0, b0);
        float2 v1 = make_float2(a1, b1);
        *(float2*)&out[(b*CC + 2*j  )*HWP + pix0] = v0;
        *(float2*)&out[(b*CC + 2*j+1)*HWP + pix0] = v1;
    }
}

// ---------------------------------------------------------------------------
extern "C" void kernel_launch(void* const* d_in, const int* in_sizes, int n_in,
                              void* d_out, int out_size)
{
    const float* x      = (const float*)d_in[0];
    const float* conv_w = (const float*)d_in[1];
    const float* conv_b = (const float*)d_in[2];
    const float* off_w  = (const float*)d_in[3];
    const float* off_b  = (const float*)d_in[4];
    const float* dw     = (const float*)d_in[5];
    const float* db     = (const float*)d_in[6];
    float* out = (float*)d_out;

    const int blocks = BB*HH*WW / 256;   // 1024

    conv1_kernel  <<<blocks, 256>>>(x, conv_w, conv_b);
    offconv_kernel<<<blocks, 256>>>(off_w, off_b);

    const int smem3_bytes = (576*64 + 64) * sizeof(float);   // 147712
    cudaFuncSetAttribute(deform_kernel,
                         cudaFuncAttributeMaxDynamicSharedMemorySize, smem3_bytes);
    deform_kernel <<<blocks/2, 256, smem3_bytes>>>(dw, db, out);
}